// round 15
// baseline (speedup 1.0000x reference)
#include <cuda_runtime.h>
#include <cuda_bf16.h>
#include <cstdint>

// MaxBlurPooling1D: x (16, 8192, 256) f32 -> z (16, 4096, 256) f32
// z[b,j,c] = w0*m[2j-1] + w1*m[2j] + w2*m[2j+1] + w3*m[2j+2]
//   m[l] = max(x[l], x[l+1]) for l<=L-2 ; m[L-1] = x[L-1] ; m[-1] = m[L] = 0
//
// Round-14: persistent double-buffered TMA pipeline.
// R12 (1-shot TMA, 6 slots) = 26.7us/77.3%; R13 (2-stage, 3 slots) = 28.1us
// -> the controlling variable is CONTINUOUS pending loads per SM slot.
// Persistent blocks (3/SM, grid = 3*num_SMs) with 2x35KB buffers: each
// iteration prefetches chunk i+1 into the spare buffer, then computes chunk
// i -> every slot always has one bulk copy in flight; no exit/restart gaps.
// Work split 4096 chunks over 456 lanes = 8.98 avg / 9 max (~0.2% tail).

#define L_DIM  8192
#define CF     256                 // f32 channels per row
#define C4     64                  // float4 lanes per row
#define J_OUT  4096
#define JPT    16                  // output rows per chunk
#define ROWB   1024                // bytes per input row
#define TILE_ROWS 35               // max rows per chunk footprint
#define TILE_BYTES (TILE_ROWS * ROWB)
#define SMEM_BYTES (256 + 2 * TILE_BYTES)
#define NCHUNK (16 * (J_OUT / JPT))    // 4096

__device__ __forceinline__ float4 f4max(float4 a, float4 b) {
    return make_float4(fmaxf(a.x, b.x), fmaxf(a.y, b.y),
                       fmaxf(a.z, b.z), fmaxf(a.w, b.w));
}

__device__ __forceinline__ void mbar_wait(uint32_t mbar_u32, uint32_t phase) {
    uint32_t ready = 0;
    while (!ready) {
        asm volatile(
            "{\n\t.reg .pred p;\n\t"
            "mbarrier.try_wait.parity.acquire.cta.shared::cta.b64 p, [%1], %2, 0x989680;\n\t"
            "selp.b32 %0, 1, 0, p;\n\t}"
            : "=r"(ready) : "r"(mbar_u32), "r"(phase) : "memory");
    }
}

// Issue the bulk copy for chunk cid into buffer (thread 0 only).
__device__ __forceinline__ void issue_chunk(const float* __restrict__ x,
                                            int cid, uint32_t dst, uint32_t mb) {
    const int b  = cid >> 8;                  // 256 chunks per batch
    const int j0 = (cid & 255) * JPT;
    const int start = (j0 == 0) ? 0 : (2 * j0 - 1);
    const int end   = min(L_DIM, 2 * j0 + 34);
    const uint32_t nb = (uint32_t)((end - start) * ROWB);
    const char* src = (const char*)(x + (size_t)b * L_DIM * CF)
                    + (size_t)start * ROWB;
    asm volatile("mbarrier.arrive.expect_tx.shared.b64 _, [%0], %1;"
                 :: "r"(mb), "r"(nb) : "memory");
    asm volatile("cp.async.bulk.shared::cta.global.mbarrier::complete_tx::bytes "
                 "[%0], [%1], %2, [%3];"
                 :: "r"(dst), "l"(src), "r"(nb), "r"(mb) : "memory");
}

__global__ void __launch_bounds__(128)
mbp1d_persist_kernel(const float* __restrict__ x,
                     const float* __restrict__ blur,
                     const float* __restrict__ avg,
                     float4*      __restrict__ z)
{
    extern __shared__ __align__(128) char smem[];
    uint64_t* mbar0 = (uint64_t*)smem;                // [0:8)
    uint64_t* mbar1 = (uint64_t*)(smem + 8);          // [8:16)
    float4* tiles[2] = { (float4*)(smem + 256),
                         (float4*)(smem + 256 + TILE_BYTES) };

    const int c   = threadIdx.x;                      // 0..63 float4 lane
    const int ty  = threadIdx.y;                      // 0..1
    const int tid = ty * 64 + c;

    const uint32_t mb[2] = { (uint32_t)__cvta_generic_to_shared(mbar0),
                             (uint32_t)__cvta_generic_to_shared(mbar1) };
    const uint32_t tu[2] = { (uint32_t)__cvta_generic_to_shared(tiles[0]),
                             (uint32_t)__cvta_generic_to_shared(tiles[1]) };

    if (tid == 0) {
        asm volatile("mbarrier.init.shared.b64 [%0], 1;" :: "r"(mb[0]));
        asm volatile("mbarrier.init.shared.b64 [%0], 1;" :: "r"(mb[1]));
    }
    __syncthreads();

    // Weights: fold blur (3-tap) and avg (2-tap) into 4 taps over m[].
    const float b0 = blur[0], b1 = blur[1], b2 = blur[2];
    const float a0 = avg[0],  a1 = avg[1];
    const float w0 = a0 * b0;
    const float w1 = a0 * b1 + a1 * b0;
    const float w2 = a0 * b2 + a1 * b1;
    const float w3 = a1 * b2;

    const float4 zero = make_float4(0.f, 0.f, 0.f, 0.f);
    const int G = gridDim.x;

    uint32_t par0 = 0, par1 = 0;
    int it = 0;

    for (int cid = blockIdx.x; cid < NCHUNK; cid += G, ++it) {
        const int buf = it & 1;

        // First iteration: kick off this chunk's load.
        if (it == 0 && tid == 0) issue_chunk(x, cid, tu[buf], mb[buf]);
        // Prefetch next chunk into the spare buffer (safe: its previous
        // compute finished before last iteration's __syncthreads).
        const int nxt = cid + G;
        if (nxt < NCHUNK && tid == 0) issue_chunk(x, nxt, tu[buf ^ 1], mb[buf ^ 1]);

        // Wait for current buffer.
        if (buf == 0) { mbar_wait(mb[0], par0); par0 ^= 1; }
        else          { mbar_wait(mb[1], par1); par1 ^= 1; }

        // ---- compute chunk cid from tiles[buf] ----
        const int bb = cid >> 8;
        const int j0 = (cid & 255) * JPT;
        const int start = (j0 == 0) ? 0 : (2 * j0 - 1);

        const float4* S  = tiles[buf] + c;            // row stride C4
        const int     js = j0 + 8 * ty;               // 8 outputs per thread
        float4*       zb = z + ((size_t)bb * J_OUT + js) * C4 + c;

        float4 mA, mB, xlast;
        {
            const float4 x0 = S[(2 * js - start) * C4];
            const float4 x1 = S[(2 * js + 1 - start) * C4];
            mA = (js == 0) ? zero : f4max(S[(2 * js - 1 - start) * C4], x0);
            mB = f4max(x0, x1);
            xlast = x1;
        }

        #pragma unroll
        for (int t = 0; t < 8; ++t) {
            const int j  = js + t;
            const int r2 = 2 * j + 2;
            float4 mC, mD;
            if (r2 < L_DIM) {
                const float4 x2 = S[(r2 - start) * C4];
                const float4 x3 = S[(r2 + 1 - start) * C4];
                mC = f4max(xlast, x2);                // m[2j+1]
                mD = f4max(x2, x3);                   // m[2j+2]
                xlast = x3;
            } else {
                // j = 4095: m[8191] = x[8191] (NEG_INF pad), m[8192] = 0
                mC = xlast;
                mD = zero;
            }

            float4 o;
            o.x = w0 * mA.x + w1 * mB.x + w2 * mC.x + w3 * mD.x;
            o.y = w0 * mA.y + w1 * mB.y + w2 * mC.y + w3 * mD.y;
            o.z = w0 * mA.z + w1 * mB.z + w2 * mC.z + w3 * mD.z;
            o.w = w0 * mA.w + w1 * mB.w + w2 * mC.w + w3 * mD.w;
            zb[(size_t)t * C4] = o;

            mA = mC;
            mB = mD;
        }

        // All threads done with tiles[buf] before it can be re-filled.
        __syncthreads();
    }
}

extern "C" void kernel_launch(void* const* d_in, const int* in_sizes, int n_in,
                              void* d_out, int out_size)
{
    const float* x    = (const float*)d_in[0];     // (16, 8192, 256) f32
    const float* blur = (const float*)d_in[1];     // (3,1,1)
    const float* avg  = (const float*)d_in[2];     // (2,1,1)
    float4*      z    = (float4*)d_out;            // (16, 4096, 256) f32

    (void)in_sizes; (void)n_in; (void)out_size;

    cudaFuncSetAttribute(mbp1d_persist_kernel,
                         cudaFuncAttributeMaxDynamicSharedMemorySize, SMEM_BYTES);

    int nsm = 148;
    cudaDeviceGetAttribute(&nsm, cudaDevAttrMultiProcessorCount, 0);

    dim3 block(C4, 2);                             // (64, 2) = 128 threads
    dim3 grid(3 * nsm);                            // persistent: 3 blocks/SM
    mbp1d_persist_kernel<<<grid, block, SMEM_BYTES>>>(x, blur, avg, z);
}

// round 16
// speedup vs baseline: 1.0544x; 1.0544x over previous
#include <cuda_runtime.h>
#include <cuda_bf16.h>
#include <cstdint>

// MaxBlurPooling1D: x (16, 8192, 256) f32 -> z (16, 4096, 256) f32
// z[b,j,c] = w0*m[2j-1] + w1*m[2j] + w2*m[2j+1] + w3*m[2j+2]
//   m[l] = max(x[l], x[l+1]) for l<=L-2 ; m[L-1] = x[L-1] ; m[-1] = m[L] = 0
//
// Round-15: R12 structure (one-shot TMA per block; co-resident blocks
// provide the pipelining), chunk halved: JPT=8 -> 19-row tile (19.5KB)
// -> 11 blocks/SM instead of 6. Evidence R12/R13/R14: DRAM% tracks the
// number of concurrently-pending bulk copies per SM (6->77%, 3->66-74%).
// 11 slots/SM ≈ 209KB in flight, 1408 thr/SM compute, 8192 blocks.

#define L_DIM  8192
#define CF     256                 // f32 channels per row
#define C4     64                  // float4 lanes per row
#define J_OUT  4096
#define JPT    8                   // output rows per block
#define ROWB   1024                // bytes per input row
#define TILE_ROWS 19               // max rows per chunk footprint
#define SMEM_BYTES (128 + TILE_ROWS * ROWB)

__device__ __forceinline__ float4 f4max(float4 a, float4 b) {
    return make_float4(fmaxf(a.x, b.x), fmaxf(a.y, b.y),
                       fmaxf(a.z, b.z), fmaxf(a.w, b.w));
}

__global__ void __launch_bounds__(128)
mbp1d_tma_kernel(const float* __restrict__ x,
                 const float* __restrict__ blur,
                 const float* __restrict__ avg,
                 float4*      __restrict__ z)
{
    extern __shared__ __align__(128) char smem[];
    uint64_t* mbar = (uint64_t*)smem;                 // [0:8)
    float4*   tile = (float4*)(smem + 128);           // 19 rows x 1KB

    const int c   = threadIdx.x;                      // 0..63 float4 lane
    const int ty  = threadIdx.y;                      // 0..1
    const int tid = ty * 64 + c;
    const int b   = blockIdx.y;                       // batch
    const int j0  = blockIdx.x * JPT;                 // first output row of chunk

    // Input footprint: rows [start, end) of batch b.
    const int start  = (j0 == 0) ? 0 : (2 * j0 - 1);
    const int end    = min(L_DIM, 2 * j0 + 18);
    const int nbytes = (end - start) * ROWB;

    const uint32_t mbar_u32 = (uint32_t)__cvta_generic_to_shared(mbar);
    const uint32_t tile_u32 = (uint32_t)__cvta_generic_to_shared(tile);

    if (tid == 0) {
        asm volatile("mbarrier.init.shared.b64 [%0], 1;" :: "r"(mbar_u32));
    }
    __syncthreads();

    if (tid == 0) {
        asm volatile("mbarrier.arrive.expect_tx.shared.b64 _, [%0], %1;"
                     :: "r"(mbar_u32), "r"((uint32_t)nbytes) : "memory");
        const char* src = (const char*)(x + (size_t)b * L_DIM * CF)
                        + (size_t)start * ROWB;
        asm volatile("cp.async.bulk.shared::cta.global.mbarrier::complete_tx::bytes "
                     "[%0], [%1], %2, [%3];"
                     :: "r"(tile_u32), "l"(src), "r"((uint32_t)nbytes),
                        "r"(mbar_u32) : "memory");
    }

    // Wait for the bulk copy (parity 0; single use).
    {
        uint32_t ready = 0;
        while (!ready) {
            asm volatile(
                "{\n\t.reg .pred p;\n\t"
                "mbarrier.try_wait.parity.acquire.cta.shared::cta.b64 p, [%1], 0, 0x989680;\n\t"
                "selp.b32 %0, 1, 0, p;\n\t}"
                : "=r"(ready) : "r"(mbar_u32) : "memory");
        }
    }

    // Weights: fold blur (3-tap) and avg (2-tap) into 4 taps over m[].
    const float b0 = blur[0], b1 = blur[1], b2 = blur[2];
    const float a0 = avg[0],  a1 = avg[1];
    const float w0 = a0 * b0;
    const float w1 = a0 * b1 + a1 * b0;
    const float w2 = a0 * b2 + a1 * b1;
    const float w3 = a1 * b2;

    // Compute from SMEM. ty splits the chunk: 4 outputs each.
    const float4* S  = tile + c;                      // row stride C4
    const int     js = j0 + 4 * ty;                   // first output for this thread
    float4*       zb = z + ((size_t)b * J_OUT + js) * C4 + c;

    const float4 zero = make_float4(0.f, 0.f, 0.f, 0.f);

    // Rolling state: mA = m[2j-1], mB = m[2j], xlast = x[2j+1]
    float4 mA, mB, xlast;
    {
        const float4 x0 = S[(2 * js - start) * C4];
        const float4 x1 = S[(2 * js + 1 - start) * C4];
        mA = (js == 0) ? zero : f4max(S[(2 * js - 1 - start) * C4], x0);
        mB = f4max(x0, x1);
        xlast = x1;
    }

    #pragma unroll
    for (int t = 0; t < 4; ++t) {
        const int j  = js + t;
        const int r2 = 2 * j + 2;
        float4 mC, mD;
        if (r2 < L_DIM) {
            const float4 x2 = S[(r2 - start) * C4];
            const float4 x3 = S[(r2 + 1 - start) * C4];
            mC = f4max(xlast, x2);                    // m[2j+1]
            mD = f4max(x2, x3);                       // m[2j+2]
            xlast = x3;
        } else {
            // j = 4095: m[8191] = x[8191] (NEG_INF pad), m[8192] = 0 (zero pad)
            mC = xlast;
            mD = zero;
        }

        float4 o;
        o.x = w0 * mA.x + w1 * mB.x + w2 * mC.x + w3 * mD.x;
        o.y = w0 * mA.y + w1 * mB.y + w2 * mC.y + w3 * mD.y;
        o.z = w0 * mA.z + w1 * mB.z + w2 * mC.z + w3 * mD.z;
        o.w = w0 * mA.w + w1 * mB.w + w2 * mC.w + w3 * mD.w;
        zb[(size_t)t * C4] = o;

        mA = mC;
        mB = mD;
    }
}

extern "C" void kernel_launch(void* const* d_in, const int* in_sizes, int n_in,
                              void* d_out, int out_size)
{
    const float* x    = (const float*)d_in[0];     // (16, 8192, 256) f32
    const float* blur = (const float*)d_in[1];     // (3,1,1)
    const float* avg  = (const float*)d_in[2];     // (2,1,1)
    float4*      z    = (float4*)d_out;            // (16, 4096, 256) f32

    (void)in_sizes; (void)n_in; (void)out_size;

    dim3 block(C4, 2);                             // (64, 2) = 128 threads
    dim3 grid(J_OUT / JPT, 16);                    // (512, 16) = 8192 blocks
    mbp1d_tma_kernel<<<grid, block, SMEM_BYTES>>>(x, blur, avg, z);
}